// round 5
// baseline (speedup 1.0000x reference)
#include <cuda_runtime.h>

#define BN   32768      // B*N
#define NPTS 8192
#define KNN  16

__device__ float4 g_pts[BN];
__device__ int    g_idx[BN * KNN];
__device__ float  g_lt[(size_t)BN * 192];

// ---------------------------------------------------------------------------
// 1. pack (x,y,z, sq) per point; sq replicates XLA: ((x*x)+(y*y))+(z*z),
//    every op individually rounded (no FMA contraction)
// ---------------------------------------------------------------------------
__global__ void pack_kernel(const float* __restrict__ xytp) {
    int i = blockIdx.x * blockDim.x + threadIdx.x;
    float4 p = ((const float4*)xytp)[i];
    float xx = __fmul_rn(p.x, p.x);
    float yy = __fmul_rn(p.y, p.y);
    float zz = __fmul_rn(p.z, p.z);
    p.w = __fadd_rn(__fadd_rn(xx, yy), zz);
    g_pts[i] = p;
}

// ---------------------------------------------------------------------------
// 2. brute-force kNN replicating XLA fp32 arithmetic exactly:
//    dot = fmaf(z,z', fmaf(y,y', rn(x*x')))      (GEMM ascending-k fma chain)
//    d2  = rn( rn(sq_i + sq_j) - rn(2*dot) )     (elementwise, separate ops)
// ---------------------------------------------------------------------------
__global__ void __launch_bounds__(64) knn_kernel() {
    const int TS = 256;
    __shared__ float4 tile[TS];
    int b = blockIdx.y;
    int q = blockIdx.x * 64 + threadIdx.x;
    const float4* pts = g_pts + b * NPTS;
    float4 me = pts[q];

    float best[KNN];
    int   bidx[KNN];
#pragma unroll
    for (int i = 0; i < KNN; i++) { best[i] = 3.4e38f; bidx[i] = 0; }

    for (int t0 = 0; t0 < NPTS; t0 += TS) {
        __syncthreads();
#pragma unroll
        for (int i = 0; i < TS / 64; i++)
            tile[threadIdx.x + i * 64] = pts[t0 + threadIdx.x + i * 64];
        __syncthreads();
#pragma unroll 4
        for (int j = 0; j < TS; j++) {
            float4 p = tile[j];
            float dot = __fmaf_rn(me.z, p.z,
                         __fmaf_rn(me.y, p.y,
                          __fmul_rn(me.x, p.x)));
            float t1 = __fadd_rn(me.w, p.w);
            float d  = __fsub_rn(t1, __fmul_rn(2.0f, dot));
            if (d < best[KNN - 1]) {
                int id = t0 + j;
#pragma unroll
                for (int s = KNN - 1; s >= 0; --s) {
                    if (s > 0 && d < best[s - 1]) {
                        best[s] = best[s - 1]; bidx[s] = bidx[s - 1];
                    } else {
                        best[s] = d; bidx[s] = id;
                        break;
                    }
                }
            }
        }
    }
    int base = (b * NPTS + q) * KNN;
#pragma unroll
    for (int i = 0; i < KNN; i++) g_idx[base + i] = bidx[i];
}

// ---------------------------------------------------------------------------
// 3. lt = features @ lt_w + lt_b   (fp32, 32768x64 @ 64x192)
// ---------------------------------------------------------------------------
__global__ void __launch_bounds__(256) lt_kernel(const float* __restrict__ feat,
                                                 const float* __restrict__ w,
                                                 const float* __restrict__ bias) {
    __shared__ float fs[32][64];
    int row0 = blockIdx.x * 32;
    for (int i = threadIdx.x; i < 32 * 64; i += 256)
        fs[i >> 6][i & 63] = feat[row0 * 64 + i];
    __syncthreads();

    int c = threadIdx.x;
    if (c < 192) {
        float wreg[64];
#pragma unroll
        for (int k = 0; k < 64; k++) wreg[k] = w[k * 192 + c];
        float bc = bias[c];
        for (int r = 0; r < 32; r++) {
            float acc = bc;
#pragma unroll
            for (int k = 0; k < 64; k++) acc = fmaf(fs[r][k], wreg[k], acc);
            g_lt[(size_t)(row0 + r) * 192 + c] = acc;
        }
    }
}

// ---------------------------------------------------------------------------
// 4. fused: gather -> delta MLP -> pre -> LN -> softmax(k) -> output
//    one warp per point; lane owns channels (lane, lane+32)
// ---------------------------------------------------------------------------
__global__ void __launch_bounds__(128) fused_kernel(
    const float* __restrict__ xytp,
    const float* __restrict__ pe_w1, const float* __restrict__ pe_b1,
    const float* __restrict__ pe_w2, const float* __restrict__ pe_b2,
    const float* __restrict__ ln_g,  const float* __restrict__ ln_b,
    float* __restrict__ out)
{
    __shared__ float  W2s[64 * 64];
    __shared__ float4 rels[4][16];
    __shared__ float  HS[4][64][20];   // HS[w][j][k] = h[k][j]; pad 20 keeps float4 rows aligned

    int tid = threadIdx.x, w = tid >> 5, lane = tid & 31;
    for (int i = tid; i < 4096; i += 128) W2s[i] = pe_w2[i];

    int pt = blockIdx.x * 4 + w;
    int b  = pt >> 13;
    int c0 = lane, c1 = lane + 32;

    float w1a[4], w1b[4];
#pragma unroll
    for (int d = 0; d < 4; d++) { w1a[d] = pe_w1[d * 64 + c0]; w1b[d] = pe_w1[d * 64 + c1]; }
    float b10 = pe_b1[c0], b11 = pe_b1[c1];
    float b20 = pe_b2[c0], b21 = pe_b2[c1];
    float g0  = ln_g[c0],  g1  = ln_g[c1];
    float q0  = ln_b[c0],  q1  = ln_b[c1];

    const int* idxp = g_idx + pt * KNN;
    float4 ctr = ((const float4*)xytp)[pt];
    if (lane < 16) {
        int nb = idxp[lane];
        float4 p = ((const float4*)xytp)[b * NPTS + nb];
        rels[w][lane] = make_float4(ctr.x - p.x, ctr.y - p.y, ctr.z - p.z, ctr.w - p.w);
    }
    __syncthreads();   // W2s (cross-warp) + rels

    // stage A: h = relu(rel @ W1 + b1), stored transposed into HS
#pragma unroll
    for (int k = 0; k < KNN; k++) {
        float4 r = rels[w][k];
        float h0 = fmaf(r.w, w1a[3], fmaf(r.z, w1a[2], fmaf(r.y, w1a[1], fmaf(r.x, w1a[0], b10))));
        float h1 = fmaf(r.w, w1b[3], fmaf(r.z, w1b[2], fmaf(r.y, w1b[1], fmaf(r.x, w1b[0], b11))));
        HS[w][c0][k] = fmaxf(h0, 0.f);
        HS[w][c1][k] = fmaxf(h1, 0.f);
    }
    __syncwarp();

    // stage B: delta = h @ W2 + b2 ; accumulators in registers
    float d0[KNN], d1[KNN];
#pragma unroll
    for (int k = 0; k < KNN; k++) { d0[k] = b20; d1[k] = b21; }
#pragma unroll 4
    for (int j = 0; j < 64; j++) {
        float wv0 = W2s[j * 64 + c0];
        float wv1 = W2s[j * 64 + c1];
        const float4* hr = (const float4*)(&HS[w][j][0]);
        float hv[16];
        ((float4*)hv)[0] = hr[0]; ((float4*)hv)[1] = hr[1];
        ((float4*)hv)[2] = hr[2]; ((float4*)hv)[3] = hr[3];
#pragma unroll
        for (int k = 0; k < KNN; k++) {
            d0[k] = fmaf(hv[k], wv0, d0[k]);
            d1[k] = fmaf(hv[k], wv1, d1[k]);
        }
    }

    // epilogue: gather psi/alpha, pre, LN (butterfly), softmax over k, output
    const float* ltb = g_lt + (size_t)(b * NPTS) * 192;
    int n = pt & (NPTS - 1);
    float vp0 = ltb[(size_t)n * 192 + c0];
    float vp1 = ltb[(size_t)n * 192 + c1];

    float a0[KNN], a1[KNN], p0[KNN], p1[KNN];
#pragma unroll
    for (int k = 0; k < KNN; k++) {
        int nb = idxp[k];
        const float* lr = ltb + (size_t)nb * 192;
        float ps0 = lr[64 + c0],  ps1 = lr[64 + c1];
        float al0 = lr[128 + c0], al1 = lr[128 + c1];
        float pr0 = (vp0 - ps0) + d0[k];
        float pr1 = (vp1 - ps1) + d1[k];
        a0[k] = al0 + d0[k];
        a1[k] = al1 + d1[k];
        float sm = pr0 + pr1;
        float sq = fmaf(pr0, pr0, pr1 * pr1);
#pragma unroll
        for (int off = 16; off > 0; off >>= 1) {
            sm += __shfl_xor_sync(0xffffffffu, sm, off);
            sq += __shfl_xor_sync(0xffffffffu, sq, off);
        }
        float mu  = sm * (1.0f / 64.0f);
        float var = fmaf(-mu, mu, sq * (1.0f / 64.0f));
        float rs  = rsqrtf(var + 1e-5f);
        p0[k] = fmaf((pr0 - mu) * rs, g0, q0) * 0.125f;   // /sqrt(64)
        p1[k] = fmaf((pr1 - mu) * rs, g1, q1) * 0.125f;
    }

    float m0 = -3.4e38f, m1 = -3.4e38f;
#pragma unroll
    for (int k = 0; k < KNN; k++) { m0 = fmaxf(m0, p0[k]); m1 = fmaxf(m1, p1[k]); }
    float z0 = 0.f, z1 = 0.f, o0 = 0.f, o1 = 0.f;
#pragma unroll
    for (int k = 0; k < KNN; k++) {
        float e0 = __expf(p0[k] - m0);
        float e1 = __expf(p1[k] - m1);
        z0 += e0; z1 += e1;
        o0 = fmaf(e0, a0[k], o0);
        o1 = fmaf(e1, a1[k], o1);
    }
    out[(size_t)pt * 64 + c0] = o0 / z0;
    out[(size_t)pt * 64 + c1] = o1 / z1;
}

// ---------------------------------------------------------------------------
extern "C" void kernel_launch(void* const* d_in, const int* in_sizes, int n_in,
                              void* d_out, int out_size) {
    const float* xytp     = (const float*)d_in[0];
    const float* features = (const float*)d_in[1];
    const float* pe_w1    = (const float*)d_in[2];
    const float* pe_b1    = (const float*)d_in[3];
    const float* pe_w2    = (const float*)d_in[4];
    const float* pe_b2    = (const float*)d_in[5];
    const float* lt_w     = (const float*)d_in[6];
    const float* lt_b     = (const float*)d_in[7];
    const float* ln_g     = (const float*)d_in[8];
    const float* ln_b     = (const float*)d_in[9];
    float* out = (float*)d_out;

    pack_kernel<<<BN / 256, 256>>>(xytp);
    dim3 kg(NPTS / 64, 4);
    knn_kernel<<<kg, 64>>>();
    lt_kernel<<<BN / 32, 256>>>(features, lt_w, lt_b);
    fused_kernel<<<BN / 4, 128>>>(xytp, pe_w1, pe_b1, pe_w2, pe_b2, ln_g, ln_b, out);
}

// round 6
// speedup vs baseline: 3.1975x; 3.1975x over previous
#include <cuda_runtime.h>

#define BN   32768      // B*N
#define NPTS 8192
#define KNN  16
#define CH   4          // candidate chunks per query
#define CSZ  (NPTS / CH)

__device__ float4 g_pts[BN];
__device__ int    g_idx[BN * KNN];
__device__ float  g_lt[(size_t)BN * 192];
__device__ float  g_pd[BN * CH * KNN];   // per-chunk sorted top-16 distances
__device__ int    g_pi[BN * CH * KNN];   // per-chunk sorted top-16 indices

#define DINF 3.4e38f

// ---------------------------------------------------------------------------
// branchless stable sorted insert into (B,I)[16]; ties (d == existing) placed
// AFTER the existing entry -> earlier-inserted (lower index) wins, matching
// jax.lax.top_k tie-break.
// ---------------------------------------------------------------------------
__device__ __forceinline__ void ins16(float d, int id, float* B, int* I) {
    if (!(d < B[15])) return;
    bool cs = true;
#pragma unroll
    for (int s = 15; s > 0; --s) {
        bool cp = d < B[s - 1];
        float nb = cp ? B[s - 1] : (cs ? d : B[s]);
        int   ni = cp ? I[s - 1] : (cs ? id : I[s]);
        B[s] = nb; I[s] = ni;
        cs = cp;
    }
    if (cs) { B[0] = d; I[0] = id; }
}

// ---------------------------------------------------------------------------
// 1. pack (x,y,z, sq); sq = ((x*x)+(y*y))+(z*z), each op separately rounded
//    (exact XLA replication -- LOAD-BEARING, do not fuse)
// ---------------------------------------------------------------------------
__global__ void pack_kernel(const float* __restrict__ xytp) {
    int i = blockIdx.x * blockDim.x + threadIdx.x;
    float4 p = ((const float4*)xytp)[i];
    float xx = __fmul_rn(p.x, p.x);
    float yy = __fmul_rn(p.y, p.y);
    float zz = __fmul_rn(p.z, p.z);
    p.w = __fadd_rn(__fadd_rn(xx, yy), zz);
    g_pts[i] = p;
}

// ---------------------------------------------------------------------------
// 2a. chunked kNN: thread = (query, chunk of 2048 candidates).
//     Exact XLA arithmetic per candidate. Lane-local 2-entry buffer +
//     warp-synchronized flush to kill divergence-union cost.
// ---------------------------------------------------------------------------
__global__ void __launch_bounds__(128) knn_part_kernel() {
    __shared__ float4 tile[256];
    int b     = blockIdx.z;
    int chunk = blockIdx.y;
    int q     = blockIdx.x * 128 + threadIdx.x;
    const float4* pts = g_pts + b * NPTS;
    float4 me = pts[q];

    float B[KNN]; int I[KNN];
#pragma unroll
    for (int i = 0; i < KNN; i++) { B[i] = DINF; I[i] = 0; }

    float bd0 = DINF, bd1 = DINF;
    int   bi0 = 0,    bi1 = 0,    bcnt = 0;
    int cbase = chunk * CSZ;

    for (int t0 = 0; t0 < CSZ; t0 += 256) {
        __syncthreads();
        tile[threadIdx.x]       = pts[cbase + t0 + threadIdx.x];
        tile[threadIdx.x + 128] = pts[cbase + t0 + threadIdx.x + 128];
        __syncthreads();
#pragma unroll 4
        for (int j = 0; j < 256; j++) {
            float4 p = tile[j];
            // exact reference arithmetic (do not modify):
            float dot = __fmaf_rn(me.z, p.z,
                         __fmaf_rn(me.y, p.y,
                          __fmul_rn(me.x, p.x)));
            float t1 = __fadd_rn(me.w, p.w);
            float d  = __fsub_rn(t1, __fmul_rn(2.0f, dot));
            if (d < B[15]) {
                if (bcnt == 0) { bd0 = d; bi0 = cbase + t0 + j; }
                else           { bd1 = d; bi1 = cbase + t0 + j; }
                bcnt++;
            }
            if (__ballot_sync(0xffffffffu, bcnt >= 2)) {
                ins16(bd0, bi0, B, I);
                ins16(bd1, bi1, B, I);
                bd0 = DINF; bd1 = DINF; bcnt = 0;
            }
        }
    }
    if (__ballot_sync(0xffffffffu, bcnt > 0)) {
        ins16(bd0, bi0, B, I);
        ins16(bd1, bi1, B, I);
    }

    int obase = ((b * NPTS + q) * CH + chunk) * KNN;
#pragma unroll
    for (int i = 0; i < KNN; i++) { g_pd[obase + i] = B[i]; g_pi[obase + i] = I[i]; }
}

// ---------------------------------------------------------------------------
// 2b. merge CH sorted 16-lists -> global top-16. Insert chunk-ascending:
//     chunks are contiguous index ranges so equal-d cross-chunk ties resolve
//     to the lower index, matching the reference.
// ---------------------------------------------------------------------------
__global__ void __launch_bounds__(128) knn_merge_kernel() {
    int t = blockIdx.x * 128 + threadIdx.x;   // 0..BN-1
    float B[KNN]; int I[KNN];
#pragma unroll
    for (int i = 0; i < KNN; i++) { B[i] = DINF; I[i] = 0; }
    int base = t * CH * KNN;
#pragma unroll
    for (int c = 0; c < CH; c++) {
        for (int s = 0; s < KNN; s++) {
            float d = g_pd[base + c * KNN + s];
            if (!(d < B[15])) break;          // chunk list sorted -> rest fails too
            ins16(d, g_pi[base + c * KNN + s], B, I);
        }
    }
#pragma unroll
    for (int i = 0; i < KNN; i++) g_idx[t * KNN + i] = I[i];
}

// ---------------------------------------------------------------------------
// 3. lt = features @ lt_w + lt_b   (fp32, 32768x64 @ 64x192)
// ---------------------------------------------------------------------------
__global__ void __launch_bounds__(256) lt_kernel(const float* __restrict__ feat,
                                                 const float* __restrict__ w,
                                                 const float* __restrict__ bias) {
    __shared__ float fs[32][64];
    int row0 = blockIdx.x * 32;
    for (int i = threadIdx.x; i < 32 * 64; i += 256)
        fs[i >> 6][i & 63] = feat[row0 * 64 + i];
    __syncthreads();

    int c = threadIdx.x;
    if (c < 192) {
        float wreg[64];
#pragma unroll
        for (int k = 0; k < 64; k++) wreg[k] = w[k * 192 + c];
        float bc = bias[c];
        for (int r = 0; r < 32; r++) {
            float acc = bc;
#pragma unroll
            for (int k = 0; k < 64; k++) acc = fmaf(fs[r][k], wreg[k], acc);
            g_lt[(size_t)(row0 + r) * 192 + c] = acc;
        }
    }
}

// ---------------------------------------------------------------------------
// 4. fused: gather -> delta MLP -> pre -> LN -> softmax(k) -> output
//    one warp per point; lane owns channels (lane, lane+32)
// ---------------------------------------------------------------------------
__global__ void __launch_bounds__(128) fused_kernel(
    const float* __restrict__ xytp,
    const float* __restrict__ pe_w1, const float* __restrict__ pe_b1,
    const float* __restrict__ pe_w2, const float* __restrict__ pe_b2,
    const float* __restrict__ ln_g,  const float* __restrict__ ln_b,
    float* __restrict__ out)
{
    __shared__ float  W2s[64 * 64];
    __shared__ float4 rels[4][16];
    __shared__ float  HS[4][64][20];   // HS[w][j][k] = h[k][j]; pad 20 keeps float4 rows aligned

    int tid = threadIdx.x, w = tid >> 5, lane = tid & 31;
    for (int i = tid; i < 4096; i += 128) W2s[i] = pe_w2[i];

    int pt = blockIdx.x * 4 + w;
    int b  = pt >> 13;
    int c0 = lane, c1 = lane + 32;

    float w1a[4], w1b[4];
#pragma unroll
    for (int d = 0; d < 4; d++) { w1a[d] = pe_w1[d * 64 + c0]; w1b[d] = pe_w1[d * 64 + c1]; }
    float b10 = pe_b1[c0], b11 = pe_b1[c1];
    float b20 = pe_b2[c0], b21 = pe_b2[c1];
    float g0  = ln_g[c0],  g1  = ln_g[c1];
    float q0  = ln_b[c0],  q1  = ln_b[c1];

    const int* idxp = g_idx + pt * KNN;
    float4 ctr = ((const float4*)xytp)[pt];
    if (lane < 16) {
        int nb = idxp[lane];
        float4 p = ((const float4*)xytp)[b * NPTS + nb];
        rels[w][lane] = make_float4(ctr.x - p.x, ctr.y - p.y, ctr.z - p.z, ctr.w - p.w);
    }
    __syncthreads();   // W2s (cross-warp) + rels

    // stage A: h = relu(rel @ W1 + b1), stored transposed into HS
#pragma unroll
    for (int k = 0; k < KNN; k++) {
        float4 r = rels[w][k];
        float h0 = fmaf(r.w, w1a[3], fmaf(r.z, w1a[2], fmaf(r.y, w1a[1], fmaf(r.x, w1a[0], b10))));
        float h1 = fmaf(r.w, w1b[3], fmaf(r.z, w1b[2], fmaf(r.y, w1b[1], fmaf(r.x, w1b[0], b11))));
        HS[w][c0][k] = fmaxf(h0, 0.f);
        HS[w][c1][k] = fmaxf(h1, 0.f);
    }
    __syncwarp();

    // stage B: delta = h @ W2 + b2 ; accumulators in registers
    float d0[KNN], d1[KNN];
#pragma unroll
    for (int k = 0; k < KNN; k++) { d0[k] = b20; d1[k] = b21; }
#pragma unroll 4
    for (int j = 0; j < 64; j++) {
        float wv0 = W2s[j * 64 + c0];
        float wv1 = W2s[j * 64 + c1];
        const float4* hr = (const float4*)(&HS[w][j][0]);
        float hv[16];
        ((float4*)hv)[0] = hr[0]; ((float4*)hv)[1] = hr[1];
        ((float4*)hv)[2] = hr[2]; ((float4*)hv)[3] = hr[3];
#pragma unroll
        for (int k = 0; k < KNN; k++) {
            d0[k] = fmaf(hv[k], wv0, d0[k]);
            d1[k] = fmaf(hv[k], wv1, d1[k]);
        }
    }

    // epilogue: gather psi/alpha, pre, LN (butterfly), softmax over k, output
    const float* ltb = g_lt + (size_t)(b * NPTS) * 192;
    int n = pt & (NPTS - 1);
    float vp0 = ltb[(size_t)n * 192 + c0];
    float vp1 = ltb[(size_t)n * 192 + c1];

    float a0[KNN], a1[KNN], p0[KNN], p1[KNN];
#pragma unroll
    for (int k = 0; k < KNN; k++) {
        int nb = idxp[k];
        const float* lr = ltb + (size_t)nb * 192;
        float ps0 = lr[64 + c0],  ps1 = lr[64 + c1];
        float al0 = lr[128 + c0], al1 = lr[128 + c1];
        float pr0 = (vp0 - ps0) + d0[k];
        float pr1 = (vp1 - ps1) + d1[k];
        a0[k] = al0 + d0[k];
        a1[k] = al1 + d1[k];
        float sm = pr0 + pr1;
        float sq = fmaf(pr0, pr0, pr1 * pr1);
#pragma unroll
        for (int off = 16; off > 0; off >>= 1) {
            sm += __shfl_xor_sync(0xffffffffu, sm, off);
            sq += __shfl_xor_sync(0xffffffffu, sq, off);
        }
        float mu  = sm * (1.0f / 64.0f);
        float var = fmaf(-mu, mu, sq * (1.0f / 64.0f));
        float rs  = rsqrtf(var + 1e-5f);
        p0[k] = fmaf((pr0 - mu) * rs, g0, q0) * 0.125f;   // /sqrt(64)
        p1[k] = fmaf((pr1 - mu) * rs, g1, q1) * 0.125f;
    }

    float m0 = -3.4e38f, m1 = -3.4e38f;
#pragma unroll
    for (int k = 0; k < KNN; k++) { m0 = fmaxf(m0, p0[k]); m1 = fmaxf(m1, p1[k]); }
    float z0 = 0.f, z1 = 0.f, o0 = 0.f, o1 = 0.f;
#pragma unroll
    for (int k = 0; k < KNN; k++) {
        float e0 = __expf(p0[k] - m0);
        float e1 = __expf(p1[k] - m1);
        z0 += e0; z1 += e1;
        o0 = fmaf(e0, a0[k], o0);
        o1 = fmaf(e1, a1[k], o1);
    }
    out[(size_t)pt * 64 + c0] = o0 / z0;
    out[(size_t)pt * 64 + c1] = o1 / z1;
}

// ---------------------------------------------------------------------------
extern "C" void kernel_launch(void* const* d_in, const int* in_sizes, int n_in,
                              void* d_out, int out_size) {
    const float* xytp     = (const float*)d_in[0];
    const float* features = (const float*)d_in[1];
    const float* pe_w1    = (const float*)d_in[2];
    const float* pe_b1    = (const float*)d_in[3];
    const float* pe_w2    = (const float*)d_in[4];
    const float* pe_b2    = (const float*)d_in[5];
    const float* lt_w     = (const float*)d_in[6];
    const float* lt_b     = (const float*)d_in[7];
    const float* ln_g     = (const float*)d_in[8];
    const float* ln_b     = (const float*)d_in[9];
    float* out = (float*)d_out;

    pack_kernel<<<BN / 256, 256>>>(xytp);
    dim3 kg(NPTS / 128, CH, 4);
    knn_part_kernel<<<kg, 128>>>();
    knn_merge_kernel<<<BN / 128, 128>>>();
    lt_kernel<<<BN / 32, 256>>>(features, lt_w, lt_b);
    fused_kernel<<<BN / 4, 128>>>(xytp, pe_w1, pe_b1, pe_w2, pe_b2, ln_g, ln_b, out);
}

// round 7
// speedup vs baseline: 3.3985x; 1.0629x over previous
#include <cuda_runtime.h>

#define BN   32768      // B*N
#define NPTS 8192
#define KNN  16
#define CH   4          // candidate chunks per query
#define CSZ  (NPTS / CH)

typedef unsigned long long ull;

__device__ float4 g_pts[BN];
__device__ int    g_idx[BN * KNN];
__device__ float  g_lt[(size_t)BN * 192];
__device__ float  g_pd[BN * CH * KNN];
__device__ int    g_pi[BN * CH * KNN];

#define DINF 3.4e38f

// ---- packed f32x2 helpers (each lane is an independent exact fp32 op) -----
__device__ __forceinline__ ull pk(float a, float b) {
    ull r; asm("mov.b64 %0, {%1,%2};" : "=l"(r) : "f"(a), "f"(b)); return r;
}
__device__ __forceinline__ void upk(ull v, float& a, float& b) {
    asm("mov.b64 {%0,%1}, %2;" : "=f"(a), "=f"(b) : "l"(v));
}
__device__ __forceinline__ ull fma2(ull a, ull b, ull c) {
    ull r; asm("fma.rn.f32x2 %0, %1, %2, %3;" : "=l"(r) : "l"(a), "l"(b), "l"(c)); return r;
}
__device__ __forceinline__ ull mul2(ull a, ull b) {
    ull r; asm("mul.rn.f32x2 %0, %1, %2;" : "=l"(r) : "l"(a), "l"(b)); return r;
}
__device__ __forceinline__ ull add2(ull a, ull b) {
    ull r; asm("add.rn.f32x2 %0, %1, %2;" : "=l"(r) : "l"(a), "l"(b)); return r;
}
#define NEG2(v) ((v) ^ 0x8000000080000000ULL)   // exact sign flip of both lanes

// ---------------------------------------------------------------------------
// branchless stable sorted insert; ties keep earlier (lower index) first,
// matching jax.lax.top_k.
// ---------------------------------------------------------------------------
__device__ __forceinline__ void ins16(float d, int id, float* B, int* I) {
    if (!(d < B[15])) return;
    bool cs = true;
#pragma unroll
    for (int s = 15; s > 0; --s) {
        bool cp = d < B[s - 1];
        float nb = cp ? B[s - 1] : (cs ? d : B[s]);
        int   ni = cp ? I[s - 1] : (cs ? id : I[s]);
        B[s] = nb; I[s] = ni;
        cs = cp;
    }
    if (cs) { B[0] = d; I[0] = id; }
}

// ---------------------------------------------------------------------------
// 1. pack (x,y,z, sq); sq = ((x*x)+(y*y))+(z*z), each op separately rounded
//    (exact XLA replication -- LOAD-BEARING, do not fuse)
// ---------------------------------------------------------------------------
__global__ void pack_kernel(const float* __restrict__ xytp) {
    int i = blockIdx.x * blockDim.x + threadIdx.x;
    float4 p = ((const float4*)xytp)[i];
    float xx = __fmul_rn(p.x, p.x);
    float yy = __fmul_rn(p.y, p.y);
    float zz = __fmul_rn(p.z, p.z);
    p.w = __fadd_rn(__fadd_rn(xx, yy), zz);
    g_pts[i] = p;
}

// ---------------------------------------------------------------------------
// 2a. chunked kNN, f32x2 pair-packed distance math (bitwise == scalar):
//     dot = fma(z, fma(y, mul(x)));  d = (sqi+sqj) + (-(2*dot))
//     Lane buffer capacity 3, warp-synchronized flush at count>=2.
// ---------------------------------------------------------------------------
__global__ void __launch_bounds__(128) knn_part_kernel() {
    __shared__ float4 ta[128];   // (x0,x1,y0,y1) per candidate pair
    __shared__ float4 tb[128];   // (z0,z1,w0,w1)
    int b     = blockIdx.z;
    int chunk = blockIdx.y;
    int q     = blockIdx.x * 128 + threadIdx.x;
    const float4* pts = g_pts + b * NPTS;
    float4 me = pts[q];
    ull mex2 = pk(me.x, me.x), mey2 = pk(me.y, me.y);
    ull mez2 = pk(me.z, me.z), mew2 = pk(me.w, me.w);
    ull two2 = pk(2.0f, 2.0f);

    float B[KNN]; int I[KNN];
#pragma unroll
    for (int i = 0; i < KNN; i++) { B[i] = DINF; I[i] = 0; }

    float bd0 = DINF, bd1 = DINF, bd2 = DINF;
    int   bi0 = 0, bi1 = 0, bi2 = 0, bcnt = 0;
    int cbase = chunk * CSZ;

    for (int t0 = 0; t0 < CSZ; t0 += 256) {
        __syncthreads();
        {   // stage 256 candidates as 128 packed pairs (values copied exactly)
            float4 p0 = pts[cbase + t0 + 2 * threadIdx.x];
            float4 p1 = pts[cbase + t0 + 2 * threadIdx.x + 1];
            ta[threadIdx.x] = make_float4(p0.x, p1.x, p0.y, p1.y);
            tb[threadIdx.x] = make_float4(p0.z, p1.z, p0.w, p1.w);
        }
        __syncthreads();
#pragma unroll 4
        for (int j = 0; j < 128; j++) {
            float4 A = ta[j];
            float4 Z = tb[j];
            ull x2 = pk(A.x, A.y), y2 = pk(A.z, A.w);
            ull z2 = pk(Z.x, Z.y), w2 = pk(Z.z, Z.w);
            // exact reference arithmetic, two candidates per op:
            ull dot2 = fma2(mez2, z2, fma2(mey2, y2, mul2(mex2, x2)));
            ull t12  = add2(mew2, w2);
            ull dd   = add2(t12, NEG2(mul2(two2, dot2)));
            float d0, d1; upk(dd, d0, d1);
            bool c0 = d0 < B[15];
            bool c1 = d1 < B[15];
            if (c0 | c1) {
                int id0 = cbase + t0 + 2 * j;
                if (c0) {
                    if (bcnt == 0)      { bd0 = d0; bi0 = id0; }
                    else if (bcnt == 1) { bd1 = d0; bi1 = id0; }
                    else                { bd2 = d0; bi2 = id0; }
                    bcnt++;
                }
                if (c1) {
                    if (bcnt == 0)      { bd0 = d1; bi0 = id0 + 1; }
                    else if (bcnt == 1) { bd1 = d1; bi1 = id0 + 1; }
                    else                { bd2 = d1; bi2 = id0 + 1; }
                    bcnt++;
                }
            }
            if (__ballot_sync(0xffffffffu, bcnt >= 2)) {
                ins16(bd0, bi0, B, I);
                ins16(bd1, bi1, B, I);
                if (__ballot_sync(0xffffffffu, bcnt > 2)) ins16(bd2, bi2, B, I);
                bd0 = DINF; bd1 = DINF; bd2 = DINF; bcnt = 0;
            }
        }
    }
    if (__ballot_sync(0xffffffffu, bcnt > 0)) {
        ins16(bd0, bi0, B, I);
        ins16(bd1, bi1, B, I);
        if (__ballot_sync(0xffffffffu, bcnt > 2)) ins16(bd2, bi2, B, I);
    }

    int obase = ((b * NPTS + q) * CH + chunk) * KNN;
#pragma unroll
    for (int i = 0; i < KNN; i++) { g_pd[obase + i] = B[i]; g_pi[obase + i] = I[i]; }
}

// ---------------------------------------------------------------------------
// 2b. merge CH sorted 16-lists -> global top-16 (chunk-ascending = tie-safe)
// ---------------------------------------------------------------------------
__global__ void __launch_bounds__(128) knn_merge_kernel() {
    int t = blockIdx.x * 128 + threadIdx.x;
    float B[KNN]; int I[KNN];
#pragma unroll
    for (int i = 0; i < KNN; i++) { B[i] = DINF; I[i] = 0; }
    int base = t * CH * KNN;
#pragma unroll
    for (int c = 0; c < CH; c++) {
        for (int s = 0; s < KNN; s++) {
            float d = g_pd[base + c * KNN + s];
            if (!(d < B[15])) break;
            ins16(d, g_pi[base + c * KNN + s], B, I);
        }
    }
#pragma unroll
    for (int i = 0; i < KNN; i++) g_idx[t * KNN + i] = I[i];
}

// ---------------------------------------------------------------------------
// 3. lt = features @ lt_w + lt_b, f32x2 over k-pairs
// ---------------------------------------------------------------------------
__global__ void __launch_bounds__(256) lt_kernel(const float* __restrict__ feat,
                                                 const float* __restrict__ w,
                                                 const float* __restrict__ bias) {
    __shared__ float fs[32][64];
    int row0 = blockIdx.x * 32;
    for (int i = threadIdx.x; i < 32 * 64; i += 256)
        fs[i >> 6][i & 63] = feat[row0 * 64 + i];
    __syncthreads();

    int c = threadIdx.x;
    if (c < 192) {
        ull w2[32];
#pragma unroll
        for (int k = 0; k < 32; k++)
            w2[k] = pk(w[(2 * k) * 192 + c], w[(2 * k + 1) * 192 + c]);
        float bc = bias[c];
        for (int r = 0; r < 32; r++) {
            ull acc = pk(bc, 0.0f);
            const float2* fr = (const float2*)&fs[r][0];
#pragma unroll
            for (int k = 0; k < 32; k++) {
                float2 f = fr[k];
                acc = fma2(pk(f.x, f.y), w2[k], acc);
            }
            float ax, ay; upk(acc, ax, ay);
            g_lt[(size_t)(row0 + r) * 192 + c] = ax + ay;
        }
    }
}

// ---------------------------------------------------------------------------
// 4. fused: gather -> delta MLP (stage B in f32x2, exact) -> LN -> softmax
// ---------------------------------------------------------------------------
__global__ void __launch_bounds__(128) fused_kernel(
    const float* __restrict__ xytp,
    const float* __restrict__ pe_w1, const float* __restrict__ pe_b1,
    const float* __restrict__ pe_w2, const float* __restrict__ pe_b2,
    const float* __restrict__ ln_g,  const float* __restrict__ ln_b,
    float* __restrict__ out)
{
    __shared__ float  W2s[64 * 64];
    __shared__ float4 rels[4][16];
    __shared__ float  HS[4][64][20];

    int tid = threadIdx.x, w = tid >> 5, lane = tid & 31;
    for (int i = tid; i < 4096; i += 128) W2s[i] = pe_w2[i];

    int pt = blockIdx.x * 4 + w;
    int b  = pt >> 13;
    int c0 = lane, c1 = lane + 32;

    float w1a[4], w1b[4];
#pragma unroll
    for (int d = 0; d < 4; d++) { w1a[d] = pe_w1[d * 64 + c0]; w1b[d] = pe_w1[d * 64 + c1]; }
    float b10 = pe_b1[c0], b11 = pe_b1[c1];
    float b20 = pe_b2[c0], b21 = pe_b2[c1];
    float g0  = ln_g[c0],  g1  = ln_g[c1];
    float q0  = ln_b[c0],  q1  = ln_b[c1];

    const int* idxp = g_idx + pt * KNN;
    float4 ctr = ((const float4*)xytp)[pt];
    if (lane < 16) {
        int nb = idxp[lane];
        float4 p = ((const float4*)xytp)[b * NPTS + nb];
        rels[w][lane] = make_float4(ctr.x - p.x, ctr.y - p.y, ctr.z - p.z, ctr.w - p.w);
    }
    __syncthreads();

    // stage A: h = relu(rel @ W1 + b1), stored transposed into HS
#pragma unroll
    for (int k = 0; k < KNN; k++) {
        float4 r = rels[w][k];
        float h0 = fmaf(r.w, w1a[3], fmaf(r.z, w1a[2], fmaf(r.y, w1a[1], fmaf(r.x, w1a[0], b10))));
        float h1 = fmaf(r.w, w1b[3], fmaf(r.z, w1b[2], fmaf(r.y, w1b[1], fmaf(r.x, w1b[0], b11))));
        HS[w][c0][k] = fmaxf(h0, 0.f);
        HS[w][c1][k] = fmaxf(h1, 0.f);
    }
    __syncwarp();

    // stage B: delta = h @ W2 + b2 ; packed pairs of independent k-accumulators
    ull d0p[8], d1p[8];
#pragma unroll
    for (int m = 0; m < 8; m++) { d0p[m] = pk(b20, b20); d1p[m] = pk(b21, b21); }
#pragma unroll 4
    for (int j = 0; j < 64; j++) {
        ull wv0 = pk(W2s[j * 64 + c0], W2s[j * 64 + c0]);
        ull wv1 = pk(W2s[j * 64 + c1], W2s[j * 64 + c1]);
        const float4* hr = (const float4*)(&HS[w][j][0]);
        float hv[16];
        ((float4*)hv)[0] = hr[0]; ((float4*)hv)[1] = hr[1];
        ((float4*)hv)[2] = hr[2]; ((float4*)hv)[3] = hr[3];
#pragma unroll
        for (int m = 0; m < 8; m++) {
            ull hp = pk(hv[2 * m], hv[2 * m + 1]);
            d0p[m] = fma2(hp, wv0, d0p[m]);
            d1p[m] = fma2(hp, wv1, d1p[m]);
        }
    }
    float d0[KNN], d1[KNN];
#pragma unroll
    for (int m = 0; m < 8; m++) {
        upk(d0p[m], d0[2 * m], d0[2 * m + 1]);
        upk(d1p[m], d1[2 * m], d1[2 * m + 1]);
    }

    // epilogue: gather psi/alpha, pre, LN (butterfly), softmax over k, output
    const float* ltb = g_lt + (size_t)(b * NPTS) * 192;
    int n = pt & (NPTS - 1);
    float vp0 = ltb[(size_t)n * 192 + c0];
    float vp1 = ltb[(size_t)n * 192 + c1];

    float a0[KNN], a1[KNN], p0[KNN], p1[KNN];
#pragma unroll
    for (int k = 0; k < KNN; k++) {
        int nb = idxp[k];
        const float* lr = ltb + (size_t)nb * 192;
        float ps0 = lr[64 + c0],  ps1 = lr[64 + c1];
        float al0 = lr[128 + c0], al1 = lr[128 + c1];
        float pr0 = (vp0 - ps0) + d0[k];
        float pr1 = (vp1 - ps1) + d1[k];
        a0[k] = al0 + d0[k];
        a1[k] = al1 + d1[k];
        float sm = pr0 + pr1;
        float sq = fmaf(pr0, pr0, pr1 * pr1);
#pragma unroll
        for (int off = 16; off > 0; off >>= 1) {
            sm += __shfl_xor_sync(0xffffffffu, sm, off);
            sq += __shfl_xor_sync(0xffffffffu, sq, off);
        }
        float mu  = sm * (1.0f / 64.0f);
        float var = fmaf(-mu, mu, sq * (1.0f / 64.0f));
        float rs  = rsqrtf(var + 1e-5f);
        p0[k] = fmaf((pr0 - mu) * rs, g0, q0) * 0.125f;
        p1[k] = fmaf((pr1 - mu) * rs, g1, q1) * 0.125f;
    }

    float m0 = -3.4e38f, m1 = -3.4e38f;
#pragma unroll
    for (int k = 0; k < KNN; k++) { m0 = fmaxf(m0, p0[k]); m1 = fmaxf(m1, p1[k]); }
    float z0 = 0.f, z1 = 0.f, o0 = 0.f, o1 = 0.f;
#pragma unroll
    for (int k = 0; k < KNN; k++) {
        float e0 = __expf(p0[k] - m0);
        float e1 = __expf(p1[k] - m1);
        z0 += e0; z1 += e1;
        o0 = fmaf(e0, a0[k], o0);
        o1 = fmaf(e1, a1[k], o1);
    }
    out[(size_t)pt * 64 + c0] = o0 / z0;
    out[(size_t)pt * 64 + c1] = o1 / z1;
}

// ---------------------------------------------------------------------------
extern "C" void kernel_launch(void* const* d_in, const int* in_sizes, int n_in,
                              void* d_out, int out_size) {
    const float* xytp     = (const float*)d_in[0];
    const float* features = (const float*)d_in[1];
    const float* pe_w1    = (const float*)d_in[2];
    const float* pe_b1    = (const float*)d_in[3];
    const float* pe_w2    = (const float*)d_in[4];
    const float* pe_b2    = (const float*)d_in[5];
    const float* lt_w     = (const float*)d_in[6];
    const float* lt_b     = (const float*)d_in[7];
    const float* ln_g     = (const float*)d_in[8];
    const float* ln_b     = (const float*)d_in[9];
    float* out = (float*)d_out;

    pack_kernel<<<BN / 256, 256>>>(xytp);
    dim3 kg(NPTS / 128, CH, 4);
    knn_part_kernel<<<kg, 128>>>();
    knn_merge_kernel<<<BN / 128, 128>>>();
    lt_kernel<<<BN / 32, 256>>>(features, lt_w, lt_b);
    fused_kernel<<<BN / 4, 128>>>(xytp, pe_w1, pe_b1, pe_w2, pe_b2, ln_g, ln_b, out);
}

// round 9
// speedup vs baseline: 4.0007x; 1.1772x over previous
#include <cuda_runtime.h>

#define BN   32768      // B*N
#define NPTS 8192
#define KNN  16
#define CH   2          // candidate chunks per query
#define CSZ  (NPTS / CH)
#define CAP  24         // per-lane survivor stack capacity

typedef unsigned long long ull;

__device__ float4 g_pts[BN];
__device__ int    g_idx[BN * KNN];
__device__ float  g_lt[(size_t)BN * 192];
__device__ float  g_pd[BN * CH * KNN];
__device__ int    g_pi[BN * CH * KNN];

#define DINF 3.4e38f

// ---- packed f32x2 helpers (each lane is an independent exact fp32 op) -----
__device__ __forceinline__ ull pk(float a, float b) {
    ull r; asm("mov.b64 %0, {%1,%2};" : "=l"(r) : "f"(a), "f"(b)); return r;
}
__device__ __forceinline__ void upk(ull v, float& a, float& b) {
    asm("mov.b64 {%0,%1}, %2;" : "=f"(a), "=f"(b) : "l"(v));
}
__device__ __forceinline__ ull fma2(ull a, ull b, ull c) {
    ull r; asm("fma.rn.f32x2 %0, %1, %2, %3;" : "=l"(r) : "l"(a), "l"(b), "l"(c)); return r;
}
__device__ __forceinline__ ull mul2(ull a, ull b) {
    ull r; asm("mul.rn.f32x2 %0, %1, %2;" : "=l"(r) : "l"(a), "l"(b)); return r;
}
__device__ __forceinline__ ull add2(ull a, ull b) {
    ull r; asm("add.rn.f32x2 %0, %1, %2;" : "=l"(r) : "l"(a), "l"(b)); return r;
}
#define NEG2(v) ((v) ^ 0x8000000080000000ULL)   // exact sign flip of both lanes

// ---------------------------------------------------------------------------
// branchless stable sorted insert; ties keep earlier (lower index) first,
// matching jax.lax.top_k.
// ---------------------------------------------------------------------------
__device__ __forceinline__ void ins16(float d, int id, float* B, int* I) {
    if (!(d < B[15])) return;
    bool cs = true;
#pragma unroll
    for (int s = 15; s > 0; --s) {
        bool cp = d < B[s - 1];
        float nb = cp ? B[s - 1] : (cs ? d : B[s]);
        int   ni = cp ? I[s - 1] : (cs ? id : I[s]);
        B[s] = nb; I[s] = ni;
        cs = cp;
    }
    if (cs) { B[0] = d; I[0] = id; }
}

// drain the per-lane survivor stack (in append order => tie-break preserved)
__device__ __forceinline__ void drain(int& cnt, ull* stk, int tid,
                                      float* B, int* I) {
    for (int i = 0;; i++) {
        if (!__ballot_sync(0xffffffffu, i < cnt)) break;
        if (i < cnt) {
            ull e  = stk[i * 128 + tid];
            float d = __uint_as_float((unsigned)(e >> 32));
            int  id = (int)(unsigned)(e & 0xffffffffu);
            ins16(d, id, B, I);
        }
    }
    cnt = 0;
}

// ---------------------------------------------------------------------------
// 1. pack (x,y,z, sq); sq = ((x*x)+(y*y))+(z*z), each op separately rounded
//    (exact XLA replication -- LOAD-BEARING, do not fuse)
// ---------------------------------------------------------------------------
__global__ void pack_kernel(const float* __restrict__ xytp) {
    int i = blockIdx.x * blockDim.x + threadIdx.x;
    float4 p = ((const float4*)xytp)[i];
    float xx = __fmul_rn(p.x, p.x);
    float yy = __fmul_rn(p.y, p.y);
    float zz = __fmul_rn(p.z, p.z);
    p.w = __fadd_rn(__fadd_rn(xx, yy), zz);
    g_pts[i] = p;
}

// ---------------------------------------------------------------------------
// 2a. chunked kNN. Hot loop: f32x2 distance math + predicated survivor append
//     to a shared-memory stack. ins16 runs only in bulk drains (per tile +
//     rare overflow), killing the divergence-union cost.
// ---------------------------------------------------------------------------
__global__ void __launch_bounds__(128) knn_part_kernel() {
    __shared__ ulonglong2 ta[128];       // (x-pair, y-pair) per candidate pair
    __shared__ ulonglong2 tb[128];       // (z-pair, w-pair)
    __shared__ ull        stk[CAP * 128];

    int tid   = threadIdx.x;
    int b     = blockIdx.z;
    int chunk = blockIdx.y;
    int q     = blockIdx.x * 128 + tid;
    const float4* pts = g_pts + b * NPTS;
    float4 me = pts[q];
    ull mex2 = pk(me.x, me.x), mey2 = pk(me.y, me.y);
    ull mez2 = pk(me.z, me.z), mew2 = pk(me.w, me.w);
    ull two2 = pk(2.0f, 2.0f);

    float B[KNN]; int I[KNN];
#pragma unroll
    for (int i = 0; i < KNN; i++) { B[i] = DINF; I[i] = 0; }

    int cnt = 0;
    int cbase = chunk * CSZ;

    for (int t0 = 0; t0 < CSZ; t0 += 256) {
        __syncthreads();
        {   // stage 256 candidates as 128 packed pairs (values copied exactly)
            float4 p0 = pts[cbase + t0 + 2 * tid];
            float4 p1 = pts[cbase + t0 + 2 * tid + 1];
            ulonglong2 va, vb;
            va.x = pk(p0.x, p1.x);  va.y = pk(p0.y, p1.y);
            vb.x = pk(p0.z, p1.z);  vb.y = pk(p0.w, p1.w);
            ta[tid] = va;  tb[tid] = vb;
        }
        __syncthreads();
#pragma unroll 4
        for (int j = 0; j < 128; j++) {
            ulonglong2 A = ta[j];
            ulonglong2 Z = tb[j];
            // exact reference arithmetic, two candidates per op:
            ull dot2 = fma2(mez2, Z.x, fma2(mey2, A.y, mul2(mex2, A.x)));
            ull dd   = add2(add2(mew2, Z.y), NEG2(mul2(two2, dot2)));
            float d0, d1; upk(dd, d0, d1);
            unsigned id0 = (unsigned)(cbase + t0 + 2 * j);
            if (d0 < B[15]) {
                stk[cnt * 128 + tid] = (((ull)__float_as_uint(d0)) << 32) | id0;
                cnt++;
            }
            if (d1 < B[15]) {
                stk[cnt * 128 + tid] = (((ull)__float_as_uint(d1)) << 32) | (id0 + 1);
                cnt++;
            }
            if (__ballot_sync(0xffffffffu, cnt >= CAP - 1))
                drain(cnt, stk, tid, B, I);
        }
        drain(cnt, stk, tid, B, I);   // tighten B[15] before next tile
    }

    int obase = ((b * NPTS + q) * CH + chunk) * KNN;
#pragma unroll
    for (int i = 0; i < KNN; i++) { g_pd[obase + i] = B[i]; g_pi[obase + i] = I[i]; }
}

// ---------------------------------------------------------------------------
// 2b. merge CH sorted 16-lists -> global top-16 (chunk-ascending = tie-safe)
// ---------------------------------------------------------------------------
__global__ void __launch_bounds__(128) knn_merge_kernel() {
    int t = blockIdx.x * 128 + threadIdx.x;
    float B[KNN]; int I[KNN];
#pragma unroll
    for (int i = 0; i < KNN; i++) { B[i] = DINF; I[i] = 0; }
    int base = t * CH * KNN;
#pragma unroll
    for (int c = 0; c < CH; c++) {
        for (int s = 0; s < KNN; s++) {
            float d = g_pd[base + c * KNN + s];
            if (!(d < B[15])) break;
            ins16(d, g_pi[base + c * KNN + s], B, I);
        }
    }
#pragma unroll
    for (int i = 0; i < KNN; i++) g_idx[t * KNN + i] = I[i];
}

// ---------------------------------------------------------------------------
// 3. lt = features @ lt_w + lt_b, f32x2 over k-pairs (fs pairs read as ull)
// ---------------------------------------------------------------------------
__global__ void __launch_bounds__(256) lt_kernel(const float* __restrict__ feat,
                                                 const float* __restrict__ w,
                                                 const float* __restrict__ bias) {
    __shared__ __align__(16) float fs[32][64];
    int row0 = blockIdx.x * 32;
    for (int i = threadIdx.x; i < 32 * 64; i += 256)
        fs[i >> 6][i & 63] = feat[row0 * 64 + i];
    __syncthreads();

    int c = threadIdx.x;
    if (c < 192) {
        ull w2[32];
#pragma unroll
        for (int k = 0; k < 32; k++)
            w2[k] = pk(w[(2 * k) * 192 + c], w[(2 * k + 1) * 192 + c]);
        float bc = bias[c];
        for (int r = 0; r < 32; r++) {
            ull acc = pk(bc, 0.0f);
            const ull* fr = (const ull*)&fs[r][0];
#pragma unroll
            for (int k = 0; k < 32; k++)
                acc = fma2(fr[k], w2[k], acc);
            float ax, ay; upk(acc, ax, ay);
            g_lt[(size_t)(row0 + r) * 192 + c] = ax + ay;
        }
    }
}

// ---------------------------------------------------------------------------
// 4. fused: gather -> delta MLP (stage B f32x2, HS rows read as ull2) -> LN
//    -> softmax(k) -> output. One warp per point; lane owns (lane, lane+32).
// ---------------------------------------------------------------------------
__global__ void __launch_bounds__(128) fused_kernel(
    const float* __restrict__ xytp,
    const float* __restrict__ pe_w1, const float* __restrict__ pe_b1,
    const float* __restrict__ pe_w2, const float* __restrict__ pe_b2,
    const float* __restrict__ ln_g,  const float* __restrict__ ln_b,
    float* __restrict__ out)
{
    __shared__ float  W2s[64 * 64];
    __shared__ float4 rels[4][16];
    __shared__ __align__(16) float HS[4][64][20];   // row stride 80B (16B-mult)

    int tid = threadIdx.x, w = tid >> 5, lane = tid & 31;
    for (int i = tid; i < 4096; i += 128) W2s[i] = pe_w2[i];

    int pt = blockIdx.x * 4 + w;
    int b  = pt >> 13;
    int c0 = lane, c1 = lane + 32;

    float w1a[4], w1b[4];
#pragma unroll
    for (int d = 0; d < 4; d++) { w1a[d] = pe_w1[d * 64 + c0]; w1b[d] = pe_w1[d * 64 + c1]; }
    float b10 = pe_b1[c0], b11 = pe_b1[c1];
    float b20 = pe_b2[c0], b21 = pe_b2[c1];
    float g0  = ln_g[c0],  g1  = ln_g[c1];
    float q0  = ln_b[c0],  q1  = ln_b[c1];

    const int* idxp = g_idx + pt * KNN;
    float4 ctr = ((const float4*)xytp)[pt];
    if (lane < 16) {
        int nb = idxp[lane];
        float4 p = ((const float4*)xytp)[b * NPTS + nb];
        rels[w][lane] = make_float4(ctr.x - p.x, ctr.y - p.y, ctr.z - p.z, ctr.w - p.w);
    }
    __syncthreads();

    // stage A: h = relu(rel @ W1 + b1), stored transposed into HS
#pragma unroll
    for (int k = 0; k < KNN; k++) {
        float4 r = rels[w][k];
        float h0 = fmaf(r.w, w1a[3], fmaf(r.z, w1a[2], fmaf(r.y, w1a[1], fmaf(r.x, w1a[0], b10))));
        float h1 = fmaf(r.w, w1b[3], fmaf(r.z, w1b[2], fmaf(r.y, w1b[1], fmaf(r.x, w1b[0], b11))));
        HS[w][c0][k] = fmaxf(h0, 0.f);
        HS[w][c1][k] = fmaxf(h1, 0.f);
    }
    __syncwarp();

    // stage B: delta = h @ W2 + b2 ; packed pairs of independent k-accumulators
    ull d0p[8], d1p[8];
#pragma unroll
    for (int m = 0; m < 8; m++) { d0p[m] = pk(b20, b20); d1p[m] = pk(b21, b21); }
#pragma unroll 4
    for (int j = 0; j < 64; j++) {
        ull wv0 = pk(W2s[j * 64 + c0], W2s[j * 64 + c0]);
        ull wv1 = pk(W2s[j * 64 + c1], W2s[j * 64 + c1]);
        const ulonglong2* hr = (const ulonglong2*)&HS[w][j][0];
        ulonglong2 ha = hr[0], hb = hr[1];
        ull hp[4] = { ha.x, ha.y, hb.x, hb.y };
#pragma unroll
        for (int m = 0; m < 4; m++) {
            d0p[m] = fma2(hp[m], wv0, d0p[m]);
            d1p[m] = fma2(hp[m], wv1, d1p[m]);
        }
        ulonglong2 hc = hr[2], hd = hr[3];
        ull hq[4] = { hc.x, hc.y, hd.x, hd.y };
#pragma unroll
        for (int m = 0; m < 4; m++) {
            d0p[m + 4] = fma2(hq[m], wv0, d0p[m + 4]);
            d1p[m + 4] = fma2(hq[m], wv1, d1p[m + 4]);
        }
    }
    float d0[KNN], d1[KNN];
#pragma unroll
    for (int m = 0; m < 8; m++) {
        upk(d0p[m], d0[2 * m], d0[2 * m + 1]);
        upk(d1p[m], d1[2 * m], d1[2 * m + 1]);
    }

    // epilogue: gather psi/alpha, pre, LN (butterfly), softmax over k, output
    const float* ltb = g_lt + (size_t)(b * NPTS) * 192;
    int n = pt & (NPTS - 1);
    float vp0 = ltb[(size_t)n * 192 + c0];
    float vp1 = ltb[(size_t)n * 192 + c1];

    float a0[KNN], a1[KNN], p0[KNN], p1[KNN];
#pragma unroll
    for (int k = 0; k < KNN; k++) {
        int nb = idxp[k];
        const float* lr = ltb + (size_t)nb * 192;
        float ps0 = lr[64 + c0],  ps1 = lr[64 + c1];
        float al0 = lr[128 + c0], al1 = lr[128 + c1];
        float pr0 = (vp0 - ps0) + d0[k];
        float pr1 = (vp1 - ps1) + d1[k];
        a0[k] = al0 + d0[k];
        a1[k] = al1 + d1[k];
        float sm = pr0 + pr1;
        float sq = fmaf(pr0, pr0, pr1 * pr1);
#pragma unroll
        for (int off = 16; off > 0; off >>= 1) {
            sm += __shfl_xor_sync(0xffffffffu, sm, off);
            sq += __shfl_xor_sync(0xffffffffu, sq, off);
        }
        float mu  = sm * (1.0f / 64.0f);
        float var = fmaf(-mu, mu, sq * (1.0f / 64.0f));
        float rs  = rsqrtf(var + 1e-5f);
        p0[k] = fmaf((pr0 - mu) * rs, g0, q0) * 0.125f;
        p1[k] = fmaf((pr1 - mu) * rs, g1, q1) * 0.125f;
    }

    float m0 = -3.4e38f, m1 = -3.4e38f;
#pragma unroll
    for (int k = 0; k < KNN; k++) { m0 = fmaxf(m0, p0[k]); m1 = fmaxf(m1, p1[k]); }
    float z0 = 0.f, z1 = 0.f, o0 = 0.f, o1 = 0.f;
#pragma unroll
    for (int k = 0; k < KNN; k++) {
        float e0 = __expf(p0[k] - m0);
        float e1 = __expf(p1[k] - m1);
        z0 += e0; z1 += e1;
        o0 = fmaf(e0, a0[k], o0);
        o1 = fmaf(e1, a1[k], o1);
    }
    out[(size_t)pt * 64 + c0] = o0 / z0;
    out[(size_t)pt * 64 + c1] = o1 / z1;
}

// ---------------------------------------------------------------------------
extern "C" void kernel_launch(void* const* d_in, const int* in_sizes, int n_in,
                              void* d_out, int out_size) {
    const float* xytp     = (const float*)d_in[0];
    const float* features = (const float*)d_in[1];
    const float* pe_w1    = (const float*)d_in[2];
    const float* pe_b1    = (const float*)d_in[3];
    const float* pe_w2    = (const float*)d_in[4];
    const float* pe_b2    = (const float*)d_in[5];
    const float* lt_w     = (const float*)d_in[6];
    const float* lt_b     = (const float*)d_in[7];
    const float* ln_g     = (const float*)d_in[8];
    const float* ln_b     = (const float*)d_in[9];
    float* out = (float*)d_out;

    pack_kernel<<<BN / 256, 256>>>(xytp);
    dim3 kg(NPTS / 128, CH, 4);
    knn_part_kernel<<<kg, 128>>>();
    knn_merge_kernel<<<BN / 128, 128>>>();
    lt_kernel<<<BN / 32, 256>>>(features, lt_w, lt_b);
    fused_kernel<<<BN / 4, 128>>>(xytp, pe_w1, pe_b1, pe_w2, pe_b2, ln_g, ln_b, out);
}

// round 10
// speedup vs baseline: 4.5584x; 1.1394x over previous
#include <cuda_runtime.h>

#define BN   32768      // B*N
#define NPTS 8192
#define KNN  16
#define CH   4          // candidate chunks per query (partition, NOT duplication)
#define CSZ  (NPTS / CH)
#define CAP  24         // per-lane survivor stack capacity

typedef unsigned long long ull;

__device__ float4 g_pts[BN];
__device__ int    g_idx[BN * KNN];
__device__ float  g_lt[(size_t)BN * 192];
__device__ float  g_pd[BN * CH * KNN];
__device__ int    g_pi[BN * CH * KNN];

#define DINF 3.4e38f

// ---- packed f32x2 helpers (each lane is an independent exact fp32 op) -----
__device__ __forceinline__ ull pk(float a, float b) {
    ull r; asm("mov.b64 %0, {%1,%2};" : "=l"(r) : "f"(a), "f"(b)); return r;
}
__device__ __forceinline__ void upk(ull v, float& a, float& b) {
    asm("mov.b64 {%0,%1}, %2;" : "=f"(a), "=f"(b) : "l"(v));
}
__device__ __forceinline__ ull fma2(ull a, ull b, ull c) {
    ull r; asm("fma.rn.f32x2 %0, %1, %2, %3;" : "=l"(r) : "l"(a), "l"(b), "l"(c)); return r;
}
__device__ __forceinline__ ull mul2(ull a, ull b) {
    ull r; asm("mul.rn.f32x2 %0, %1, %2;" : "=l"(r) : "l"(a), "l"(b)); return r;
}
__device__ __forceinline__ ull add2(ull a, ull b) {
    ull r; asm("add.rn.f32x2 %0, %1, %2;" : "=l"(r) : "l"(a), "l"(b)); return r;
}

// ---------------------------------------------------------------------------
// branchless stable sorted insert; ties keep earlier (lower index) first,
// matching jax.lax.top_k.
// ---------------------------------------------------------------------------
__device__ __forceinline__ void ins16(float d, int id, float* B, int* I) {
    if (!(d < B[15])) return;
    bool cs = true;
#pragma unroll
    for (int s = 15; s > 0; --s) {
        bool cp = d < B[s - 1];
        float nb = cp ? B[s - 1] : (cs ? d : B[s]);
        int   ni = cp ? I[s - 1] : (cs ? id : I[s]);
        B[s] = nb; I[s] = ni;
        cs = cp;
    }
    if (cs) { B[0] = d; I[0] = id; }
}

// drain the per-lane survivor stack (in append order => tie-break preserved)
__device__ __forceinline__ void drain(int& cnt, ull* stk, int tid,
                                      float* B, int* I) {
    for (int i = 0;; i++) {
        if (!__ballot_sync(0xffffffffu, i < cnt)) break;
        if (i < cnt) {
            ull e  = stk[i * 128 + tid];
            float d = __uint_as_float((unsigned)(e >> 32));
            int  id = (int)(unsigned)(e & 0xffffffffu);
            ins16(d, id, B, I);
        }
    }
    cnt = 0;
}

// ---------------------------------------------------------------------------
// 1. pack (x,y,z, sq); sq = ((x*x)+(y*y))+(z*z), each op separately rounded
//    (exact XLA replication -- LOAD-BEARING, do not fuse)
// ---------------------------------------------------------------------------
__global__ void pack_kernel(const float* __restrict__ xytp) {
    int i = blockIdx.x * blockDim.x + threadIdx.x;
    float4 p = ((const float4*)xytp)[i];
    float xx = __fmul_rn(p.x, p.x);
    float yy = __fmul_rn(p.y, p.y);
    float zz = __fmul_rn(p.z, p.z);
    p.w = __fadd_rn(__fadd_rn(xx, yy), zz);
    g_pts[i] = p;
}

// ---------------------------------------------------------------------------
// 2a. chunked kNN. Query scaled by -2 (exact, commutes with rounding) so
//     d = (sqi+sqj) + dotn  bitwise == reference's (sqi+sqj) - 2*dot.
//     2 j's per iteration: 4 candidates, 4 independent f32x2 chains, 1 ballot.
// ---------------------------------------------------------------------------
__global__ void __launch_bounds__(128) knn_part_kernel() {
    __shared__ ulonglong2 ta[128];       // (x-pair, y-pair) per candidate pair
    __shared__ ulonglong2 tb[128];       // (z-pair, w-pair)
    __shared__ ull        stk[CAP * 128];

    int tid   = threadIdx.x;
    int b     = blockIdx.z;
    int chunk = blockIdx.y;
    int q     = blockIdx.x * 128 + tid;
    const float4* pts = g_pts + b * NPTS;
    float4 me = pts[q];
    ull m2x = pk(-2.0f * me.x, -2.0f * me.x);   // exact power-of-2 scale
    ull m2y = pk(-2.0f * me.y, -2.0f * me.y);
    ull m2z = pk(-2.0f * me.z, -2.0f * me.z);
    ull mw  = pk(me.w, me.w);

    float B[KNN]; int I[KNN];
#pragma unroll
    for (int i = 0; i < KNN; i++) { B[i] = DINF; I[i] = 0; }

    int cnt = 0;
    int cbase = chunk * CSZ;

    for (int t0 = 0; t0 < CSZ; t0 += 256) {
        __syncthreads();
        {   // stage 256 candidates as 128 packed pairs (values copied exactly)
            float4 p0 = pts[cbase + t0 + 2 * tid];
            float4 p1 = pts[cbase + t0 + 2 * tid + 1];
            ulonglong2 va, vb;
            va.x = pk(p0.x, p1.x);  va.y = pk(p0.y, p1.y);
            vb.x = pk(p0.z, p1.z);  vb.y = pk(p0.w, p1.w);
            ta[tid] = va;  tb[tid] = vb;
        }
        __syncthreads();
#pragma unroll 4
        for (int j = 0; j < 128; j += 2) {
            ulonglong2 A0 = ta[j],     Z0 = tb[j];
            ulonglong2 A1 = ta[j + 1], Z1 = tb[j + 1];
            // dotn = -(2*dot) bitwise; d = (sqi+sqj) - 2*dot bitwise:
            ull dn0 = fma2(m2z, Z0.x, fma2(m2y, A0.y, mul2(m2x, A0.x)));
            ull dn1 = fma2(m2z, Z1.x, fma2(m2y, A1.y, mul2(m2x, A1.x)));
            ull dd0 = add2(add2(mw, Z0.y), dn0);
            ull dd1 = add2(add2(mw, Z1.y), dn1);
            float d0, d1, d2, d3;
            upk(dd0, d0, d1);
            upk(dd1, d2, d3);
            unsigned id0 = (unsigned)(cbase + t0 + 2 * j);
            float b15 = B[15];
            if (d0 < b15) { stk[cnt * 128 + tid] = (((ull)__float_as_uint(d0)) << 32) |  id0;      cnt++; }
            if (d1 < b15) { stk[cnt * 128 + tid] = (((ull)__float_as_uint(d1)) << 32) | (id0 + 1); cnt++; }
            if (d2 < b15) { stk[cnt * 128 + tid] = (((ull)__float_as_uint(d2)) << 32) | (id0 + 2); cnt++; }
            if (d3 < b15) { stk[cnt * 128 + tid] = (((ull)__float_as_uint(d3)) << 32) | (id0 + 3); cnt++; }
            if (__ballot_sync(0xffffffffu, cnt >= CAP - 4))
                drain(cnt, stk, tid, B, I);
        }
        drain(cnt, stk, tid, B, I);   // tighten B[15] before next tile
    }

    int obase = ((b * NPTS + q) * CH + chunk) * KNN;
#pragma unroll
    for (int i = 0; i < KNN; i++) { g_pd[obase + i] = B[i]; g_pi[obase + i] = I[i]; }
}

// ---------------------------------------------------------------------------
// 2b. merge CH sorted 16-lists -> global top-16 (chunk-ascending = tie-safe)
// ---------------------------------------------------------------------------
__global__ void __launch_bounds__(128) knn_merge_kernel() {
    int t = blockIdx.x * 128 + threadIdx.x;
    float B[KNN]; int I[KNN];
#pragma unroll
    for (int i = 0; i < KNN; i++) { B[i] = DINF; I[i] = 0; }
    int base = t * CH * KNN;
#pragma unroll
    for (int c = 0; c < CH; c++) {
        for (int s = 0; s < KNN; s++) {
            float d = g_pd[base + c * KNN + s];
            if (!(d < B[15])) break;
            ins16(d, g_pi[base + c * KNN + s], B, I);
        }
    }
#pragma unroll
    for (int i = 0; i < KNN; i++) g_idx[t * KNN + i] = I[i];
}

// ---------------------------------------------------------------------------
// 3. lt = features @ lt_w + lt_b, f32x2 over k-pairs (fs pairs read as ull)
// ---------------------------------------------------------------------------
__global__ void __launch_bounds__(256) lt_kernel(const float* __restrict__ feat,
                                                 const float* __restrict__ w,
                                                 const float* __restrict__ bias) {
    __shared__ __align__(16) float fs[32][64];
    int row0 = blockIdx.x * 32;
    for (int i = threadIdx.x; i < 32 * 64; i += 256)
        fs[i >> 6][i & 63] = feat[row0 * 64 + i];
    __syncthreads();

    int c = threadIdx.x;
    if (c < 192) {
        ull w2[32];
#pragma unroll
        for (int k = 0; k < 32; k++)
            w2[k] = pk(w[(2 * k) * 192 + c], w[(2 * k + 1) * 192 + c]);
        float bc = bias[c];
        for (int r = 0; r < 32; r++) {
            ull acc = pk(bc, 0.0f);
            const ull* fr = (const ull*)&fs[r][0];
#pragma unroll
            for (int k = 0; k < 32; k++)
                acc = fma2(fr[k], w2[k], acc);
            float ax, ay; upk(acc, ax, ay);
            g_lt[(size_t)(row0 + r) * 192 + c] = ax + ay;
        }
    }
}

// ---------------------------------------------------------------------------
// 4. fused: gather -> delta MLP (stage B f32x2, HS rows read as ull2) -> LN
//    -> softmax(k) -> output. One warp per point; lane owns (lane, lane+32).
// ---------------------------------------------------------------------------
__global__ void __launch_bounds__(128) fused_kernel(
    const float* __restrict__ xytp,
    const float* __restrict__ pe_w1, const float* __restrict__ pe_b1,
    const float* __restrict__ pe_w2, const float* __restrict__ pe_b2,
    const float* __restrict__ ln_g,  const float* __restrict__ ln_b,
    float* __restrict__ out)
{
    __shared__ float  W2s[64 * 64];
    __shared__ float4 rels[4][16];
    __shared__ __align__(16) float HS[4][64][20];   // row stride 80B (16B-mult)

    int tid = threadIdx.x, w = tid >> 5, lane = tid & 31;
    for (int i = tid; i < 4096; i += 128) W2s[i] = pe_w2[i];

    int pt = blockIdx.x * 4 + w;
    int b  = pt >> 13;
    int c0 = lane, c1 = lane + 32;

    float w1a[4], w1b[4];
#pragma unroll
    for (int d = 0; d < 4; d++) { w1a[d] = pe_w1[d * 64 + c0]; w1b[d] = pe_w1[d * 64 + c1]; }
    float b10 = pe_b1[c0], b11 = pe_b1[c1];
    float b20 = pe_b2[c0], b21 = pe_b2[c1];
    float g0  = ln_g[c0],  g1  = ln_g[c1];
    float q0  = ln_b[c0],  q1  = ln_b[c1];

    const int* idxp = g_idx + pt * KNN;
    float4 ctr = ((const float4*)xytp)[pt];
    if (lane < 16) {
        int nb = idxp[lane];
        float4 p = ((const float4*)xytp)[b * NPTS + nb];
        rels[w][lane] = make_float4(ctr.x - p.x, ctr.y - p.y, ctr.z - p.z, ctr.w - p.w);
    }
    __syncthreads();

    // stage A: h = relu(rel @ W1 + b1), stored transposed into HS
#pragma unroll
    for (int k = 0; k < KNN; k++) {
        float4 r = rels[w][k];
        float h0 = fmaf(r.w, w1a[3], fmaf(r.z, w1a[2], fmaf(r.y, w1a[1], fmaf(r.x, w1a[0], b10))));
        float h1 = fmaf(r.w, w1b[3], fmaf(r.z, w1b[2], fmaf(r.y, w1b[1], fmaf(r.x, w1b[0], b11))));
        HS[w][c0][k] = fmaxf(h0, 0.f);
        HS[w][c1][k] = fmaxf(h1, 0.f);
    }
    __syncwarp();

    // stage B: delta = h @ W2 + b2 ; packed pairs of independent k-accumulators
    ull d0p[8], d1p[8];
#pragma unroll
    for (int m = 0; m < 8; m++) { d0p[m] = pk(b20, b20); d1p[m] = pk(b21, b21); }
#pragma unroll 4
    for (int j = 0; j < 64; j++) {
        ull wv0 = pk(W2s[j * 64 + c0], W2s[j * 64 + c0]);
        ull wv1 = pk(W2s[j * 64 + c1], W2s[j * 64 + c1]);
        const ulonglong2* hr = (const ulonglong2*)&HS[w][j][0];
        ulonglong2 ha = hr[0], hb = hr[1];
        ull hp[4] = { ha.x, ha.y, hb.x, hb.y };
#pragma unroll
        for (int m = 0; m < 4; m++) {
            d0p[m] = fma2(hp[m], wv0, d0p[m]);
            d1p[m] = fma2(hp[m], wv1, d1p[m]);
        }
        ulonglong2 hc = hr[2], hd = hr[3];
        ull hq[4] = { hc.x, hc.y, hd.x, hd.y };
#pragma unroll
        for (int m = 0; m < 4; m++) {
            d0p[m + 4] = fma2(hq[m], wv0, d0p[m + 4]);
            d1p[m + 4] = fma2(hq[m], wv1, d1p[m + 4]);
        }
    }
    float d0[KNN], d1[KNN];
#pragma unroll
    for (int m = 0; m < 8; m++) {
        upk(d0p[m], d0[2 * m], d0[2 * m + 1]);
        upk(d1p[m], d1[2 * m], d1[2 * m + 1]);
    }

    // epilogue: gather psi/alpha, pre, LN (butterfly), softmax over k, output
    const float* ltb = g_lt + (size_t)(b * NPTS) * 192;
    int n = pt & (NPTS - 1);
    float vp0 = ltb[(size_t)n * 192 + c0];
    float vp1 = ltb[(size_t)n * 192 + c1];

    float a0[KNN], a1[KNN], p0[KNN], p1[KNN];
#pragma unroll
    for (int k = 0; k < KNN; k++) {
        int nb = idxp[k];
        const float* lr = ltb + (size_t)nb * 192;
        float ps0 = lr[64 + c0],  ps1 = lr[64 + c1];
        float al0 = lr[128 + c0], al1 = lr[128 + c1];
        float pr0 = (vp0 - ps0) + d0[k];
        float pr1 = (vp1 - ps1) + d1[k];
        a0[k] = al0 + d0[k];
        a1[k] = al1 + d1[k];
        float sm = pr0 + pr1;
        float sq = fmaf(pr0, pr0, pr1 * pr1);
#pragma unroll
        for (int off = 16; off > 0; off >>= 1) {
            sm += __shfl_xor_sync(0xffffffffu, sm, off);
            sq += __shfl_xor_sync(0xffffffffu, sq, off);
        }
        float mu  = sm * (1.0f / 64.0f);
        float var = fmaf(-mu, mu, sq * (1.0f / 64.0f));
        float rs  = rsqrtf(var + 1e-5f);
        p0[k] = fmaf((pr0 - mu) * rs, g0, q0) * 0.125f;
        p1[k] = fmaf((pr1 - mu) * rs, g1, q1) * 0.125f;
    }

    float m0 = -3.4e38f, m1 = -3.4e38f;
#pragma unroll
    for (int k = 0; k < KNN; k++) { m0 = fmaxf(m0, p0[k]); m1 = fmaxf(m1, p1[k]); }
    float z0 = 0.f, z1 = 0.f, o0 = 0.f, o1 = 0.f;
#pragma unroll
    for (int k = 0; k < KNN; k++) {
        float e0 = __expf(p0[k] - m0);
        float e1 = __expf(p1[k] - m1);
        z0 += e0; z1 += e1;
        o0 = fmaf(e0, a0[k], o0);
        o1 = fmaf(e1, a1[k], o1);
    }
    out[(size_t)pt * 64 + c0] = o0 / z0;
    out[(size_t)pt * 64 + c1] = o1 / z1;
}

// ---------------------------------------------------------------------------
extern "C" void kernel_launch(void* const* d_in, const int* in_sizes, int n_in,
                              void* d_out, int out_size) {
    const float* xytp     = (const float*)d_in[0];
    const float* features = (const float*)d_in[1];
    const float* pe_w1    = (const float*)d_in[2];
    const float* pe_b1    = (const float*)d_in[3];
    const float* pe_w2    = (const float*)d_in[4];
    const float* pe_b2    = (const float*)d_in[5];
    const float* lt_w     = (const float*)d_in[6];
    const float* lt_b     = (const float*)d_in[7];
    const float* ln_g     = (const float*)d_in[8];
    const float* ln_b     = (const float*)d_in[9];
    float* out = (float*)d_out;

    pack_kernel<<<BN / 256, 256>>>(xytp);
    dim3 kg(NPTS / 128, CH, 4);
    knn_part_kernel<<<kg, 128>>>();
    knn_merge_kernel<<<BN / 128, 128>>>();
    lt_kernel<<<BN / 32, 256>>>(features, lt_w, lt_b);
    fused_kernel<<<BN / 4, 128>>>(xytp, pe_w1, pe_b1, pe_w2, pe_b2, ln_g, ln_b, out);
}